// round 7
// baseline (speedup 1.0000x reference)
#include <cuda_runtime.h>
#include <stdint.h>
#include <math.h>

// ---------------------------------------------------------------------------
// ProposalLayer: decode -> clip -> min-size filter -> top-12000 -> NMS(0.7)
//                -> first 2000 kept boxes (zero padded)
// R5: cub sort -> O(m^2) brute-force rank+scatter (keys unique), 1 kernel.
//     resolve widened to 1024 threads. int4 histogram scans. 11 launches.
// ---------------------------------------------------------------------------

#define NMAX    147456
#define NPRE    12000
#define NPOST   2000
#define CAP     16384
#define NMS_T   0.7f
#define WPR     188          // u64 words per mask row (ceil(12000/64))
#define TOPPAD  12032        // 188*64, padded top-box array
#define B1      4096         // stage-1 NMS coverage (64 chunks)

// ------------------------- scratch (device globals) ------------------------
__device__ unsigned int       g_keys[NMAX];
__device__ float4             g_boxes[NMAX];
__device__ int                g_hist1[65536];
__device__ int                g_hist2[65536];
__device__ unsigned int       g_T;
__device__ int                g_C1;
__device__ int                g_flag;
__device__ unsigned int       g_kthKey;
__device__ int                g_candCount;
__device__ unsigned long long g_cand[CAP];
__device__ float4             g_topBox[TOPPAD];
__device__ float              g_topArea[TOPPAD];
__device__ int                g_validTop;
__device__ unsigned long long g_mask[(size_t)NPRE * WPR];   // ~18 MB
__device__ int                g_kept;
__device__ int                g_needMore;
__device__ unsigned long long g_keptMaskG[WPR];

// ------------------------------- K0: zero ----------------------------------
__global__ void k_zero(float* __restrict__ out) {
    int i = blockIdx.x * blockDim.x + threadIdx.x;
    int stride = gridDim.x * blockDim.x;
    for (int k = i; k < 65536; k += stride) { g_hist1[k] = 0; g_hist2[k] = 0; }
    for (int k = i; k < NPOST * 4; k += stride) out[k] = 0.0f;
    if (i == 0) {
        g_candCount = 0;
        g_flag      = 0;
        g_T         = 0;
        g_C1        = 0;
        g_kthKey    = 1u;      // fallback: gather all valid (only if <NPRE valid)
        g_needMore  = 0;
        g_kept      = 0;
    }
}

// --------------------- K1: decode + clip + key + hist1 ---------------------
__global__ void k_decode(const float* __restrict__ anc,
                         const float* __restrict__ off,
                         const float* __restrict__ sc,
                         const int* __restrict__ ph,
                         const int* __restrict__ pw,
                         const int* __restrict__ ps,
                         int n) {
    int i = blockIdx.x * blockDim.x + threadIdx.x;
    if (i >= n) return;

    float H = (float)ph[0];
    float W = (float)pw[0];
    float minsz = __fmul_rn(16.0f, (float)ps[0]);

    float a0 = anc[4 * i + 0], a1 = anc[4 * i + 1];
    float a2 = anc[4 * i + 2], a3 = anc[4 * i + 3];
    float o0 = off[4 * i + 0], o1 = off[4 * i + 1];
    float o2 = off[4 * i + 2], o3 = off[4 * i + 3];

    float ah  = __fsub_rn(a2, a0);
    float aw  = __fsub_rn(a3, a1);
    float acy = __fadd_rn(a0, __fmul_rn(0.5f, ah));
    float acx = __fadd_rn(a1, __fmul_rn(0.5f, aw));
    float cy  = __fadd_rn(__fmul_rn(o0, ah), acy);
    float cx  = __fadd_rn(__fmul_rn(o1, aw), acx);
    float h   = __fmul_rn(expf(o2), ah);
    float w   = __fmul_rn(expf(o3), aw);

    float y1 = __fsub_rn(cy, __fmul_rn(0.5f, h));
    float x1 = __fsub_rn(cx, __fmul_rn(0.5f, w));
    float y2 = __fadd_rn(cy, __fmul_rn(0.5f, h));
    float x2 = __fadd_rn(cx, __fmul_rn(0.5f, w));

    y1 = fminf(fmaxf(y1, 0.0f), H);
    x1 = fminf(fmaxf(x1, 0.0f), W);
    y2 = fminf(fmaxf(y2, 0.0f), H);
    x2 = fminf(fmaxf(x2, 0.0f), W);

    float rh = __fsub_rn(y2, y1);
    float rw = __fsub_rn(x2, x1);
    bool valid = (rh >= minsz) && (rw >= minsz);

    unsigned key = 0u;
    if (valid) {
        unsigned u = __float_as_uint(sc[i]);
        key = (u & 0x80000000u) ? ~u : (u | 0x80000000u);
        if (key == 0u) key = 1u;
    }
    g_keys[i]  = key;
    g_boxes[i] = make_float4(y1, x1, y2, x2);
    if (key) atomicAdd(&g_hist1[key >> 16], 1);
}

// -------------------- K2: find threshold bin (16 high bits) ----------------
__global__ void k_find1() {
    __shared__ int part[1024];
    int t = threadIdx.x;
    const int4* h4 = (const int4*)g_hist1;
    int s = 0;
#pragma unroll
    for (int k = 0; k < 16; k++) {
        int4 v = h4[t * 16 + k];
        s += v.x + v.y + v.z + v.w;
    }
    part[t] = s;
    __syncthreads();
    for (int offs = 1; offs < 1024; offs <<= 1) {
        int v = part[t] + ((t + offs < 1024) ? part[t + offs] : 0);
        __syncthreads();
        part[t] = v;
        __syncthreads();
    }
    int Sincl = part[t];
    int Sexcl = Sincl - s;
    if (t == 0 && part[0] < NPRE) g_flag = 1;
    if (Sexcl < NPRE && Sincl >= NPRE) {
        int base = t * 64;
        int cum = Sexcl;
        for (int b = base + 63; b >= base; b--) {
            int hb = g_hist1[b];
            cum += hb;
            if (cum >= NPRE) {
                g_T  = (unsigned)b;
                g_C1 = cum - hb;
                break;
            }
        }
    }
}

// ------------------ K3: second-level histogram (16 low bits) ---------------
__global__ void k_hist2(int n) {
    int i = blockIdx.x * blockDim.x + threadIdx.x;
    if (i >= n) return;
    unsigned key = g_keys[i];
    if (key && (key >> 16) == g_T) atomicAdd(&g_hist2[key & 0xFFFFu], 1);
}

// ----------------------- K4: exact 32-bit K-th key -------------------------
__global__ void k_find2() {
    if (g_flag) return;
    __shared__ int part[1024];
    int t = threadIdx.x;
    int C1 = g_C1;
    const int4* h4 = (const int4*)g_hist2;
    int s = 0;
#pragma unroll
    for (int k = 0; k < 16; k++) {
        int4 v = h4[t * 16 + k];
        s += v.x + v.y + v.z + v.w;
    }
    part[t] = s;
    __syncthreads();
    for (int offs = 1; offs < 1024; offs <<= 1) {
        int v = part[t] + ((t + offs < 1024) ? part[t + offs] : 0);
        __syncthreads();
        part[t] = v;
        __syncthreads();
    }
    int Sincl = part[t];
    int Sexcl = Sincl - s;
    if (C1 + Sexcl < NPRE && C1 + Sincl >= NPRE) {
        int base = t * 64;
        int cum = C1 + Sexcl;
        for (int b = base + 63; b >= base; b--) {
            cum += g_hist2[b];
            if (cum >= NPRE) {
                g_kthKey = (g_T << 16) | (unsigned)b;
                break;
            }
        }
    }
}

// ----------------------------- K5: gather ----------------------------------
__global__ void k_gather(int n) {
    int i = blockIdx.x * blockDim.x + threadIdx.x;
    if (i >= n) return;
    unsigned key = g_keys[i];
    if (key && key >= g_kthKey) {
        int p = atomicAdd(&g_candCount, 1);
        if (p < CAP) {
            // composite: score key desc, then index asc (top_k tie-break)
            g_cand[p] = ((unsigned long long)key << 32) |
                        (unsigned long long)(0xFFFFFFFFu - (unsigned)i);
        }
    }
}

// --------- K6: brute-force rank (keys unique) + scatter boxes/areas --------
// rank_i = #{j : key_j > key_i}  ->  exact descending position. 64 blocks.
__global__ void __launch_bounds__(256) k_rank() {
    __shared__ unsigned long long tile[256];
    int m = g_candCount; if (m > CAP) m = CAP;
    int i = blockIdx.x * 256 + threadIdx.x;
    unsigned long long my = (i < m) ? g_cand[i] : 0ull;

    int rank = 0;
    int ntiles = (m + 255) >> 8;
    for (int t = 0; t < ntiles; t++) {
        int j = t * 256 + threadIdx.x;
        tile[threadIdx.x] = (j < m) ? g_cand[j] : 0ull;   // pad 0 never > valid key
        __syncthreads();
#pragma unroll 16
        for (int k = 0; k < 256; k++) rank += (tile[k] > my) ? 1 : 0;
        __syncthreads();
    }

    if (i < m && rank < NPRE) {
        unsigned idx = 0xFFFFFFFFu - (unsigned)my;
        float4 b = g_boxes[idx];
        g_topBox[rank]  = b;
        g_topArea[rank] = __fmul_rn(__fsub_rn(b.z, b.x), __fsub_rn(b.w, b.y));
    }
    if (i == 0) g_validTop = (m < NPRE) ? m : NPRE;
}

// --------------------------- IoU (reference-exact) -------------------------
__device__ __forceinline__ bool iou_gt(float4 a, float aa, float4 b, float ab) {
    float ty = fmaxf(a.x, b.x);
    float tx = fmaxf(a.y, b.y);
    float by = fminf(a.z, b.z);
    float bx = fminf(a.w, b.w);
    float hh = fmaxf(__fsub_rn(by, ty), 0.0f);
    float ww = fmaxf(__fsub_rn(bx, tx), 0.0f);
    float inter = __fmul_rn(hh, ww);
    float uni = __fsub_rn(__fadd_rn(aa, ab), inter);
    float iou = __fdiv_rn(inter, fmaxf(uni, 1e-9f));
    return iou > NMS_T;
}

// --------- K7: parallel suppression mask (64x64 tiles, full words) ---------
__global__ void k_mask(int rb0, int gated) {
    if (gated && !g_needMore) return;
    int rb = rb0 + blockIdx.y;
    int cb = blockIdx.x;
    if (cb > rb) return;

    __shared__ float4 cB[64];
    __shared__ float  cA[64];
    int t = threadIdx.x;
    cB[t] = g_topBox[cb * 64 + t];
    cA[t] = g_topArea[cb * 64 + t];
    __syncthreads();

    int row = rb * 64 + t;
    if (row >= NPRE) return;
    float4 rbx = g_topBox[row];
    float  ra  = g_topArea[row];

    unsigned long long word = 0ull;
    int jmax = (cb == rb) ? t : 64;   // strictly j < i
    for (int j = 0; j < jmax; j++)
        if (iou_gt(rbx, ra, cB[j], cA[j])) word |= (1ull << j);
    g_mask[(size_t)row * WPR + cb] = word;
}

// ---------- K8: greedy resolve over precomputed mask (IoU-free) ------------
__global__ void __launch_bounds__(1024, 1) k_resolve(int stage, float* __restrict__ out) {
    if (stage && !g_needMore) return;

    __shared__ unsigned long long keptMask[WPR];
    __shared__ unsigned long long diag[64];
    __shared__ int                supPrev[64];
    __shared__ unsigned long long sKl;
    __shared__ int                sKept;

    int tid  = threadIdx.x;
    int lane = tid & 31;
    int warp = tid >> 5;   // 32 warps

    int vt = g_validTop;
    int start = stage ? B1 : 0;
    int end   = stage ? vt : (vt < B1 ? vt : B1);
    int kept  = stage ? g_kept : 0;

    if (stage) { for (int w = tid; w < WPR; w += 1024) keptMask[w] = g_keptMaskG[w]; }
    else       { for (int w = tid; w < WPR; w += 1024) keptMask[w] = 0ull; }
    __syncthreads();

    for (int base = start; base < end && kept < NPOST; base += 64) {
        int cn = end - base; if (cn > 64) cn = 64;
        int cw = base >> 6;

        // suppressed-by-previously-kept: AND mask row with keptMask words
        for (int r = warp; r < cn; r += 32) {
            const unsigned long long* rowp = &g_mask[(size_t)(base + r) * WPR];
            bool any = false;
            for (int w = lane; w < cw; w += 32)
                any |= (__ldg(&rowp[w]) & keptMask[w]) != 0ull;
            unsigned bal = __ballot_sync(0xffffffffu, any);
            if (lane == 0) supPrev[r] = (bal != 0u);
        }
        if (tid < cn) diag[tid] = g_mask[(size_t)(base + tid) * WPR + cw];
        __syncthreads();

        // exact sequential greedy within the 64-chunk
        if (tid == 0) {
            unsigned long long kl = 0ull;
            int kc = kept;
            for (int i = 0; i < cn && kc < NPOST; i++) {
                if (!supPrev[i] && !(diag[i] & kl)) { kl |= (1ull << i); kc++; }
            }
            sKl = kl; sKept = kc;
            keptMask[cw] = kl;
        }
        __syncthreads();

        unsigned long long kl = sKl;
        if (tid < cn && ((kl >> tid) & 1ull)) {
            int pos = kept + __popcll(kl & ((1ull << tid) - 1ull));
            ((float4*)out)[pos] = g_topBox[base + tid];
        }
        __syncthreads();
        kept = sKept;
        __syncthreads();
    }

    if (tid == 0) {
        g_kept = kept;
        if (stage == 0) g_needMore = (kept < NPOST && vt > B1) ? 1 : 0;
    }
    for (int w = tid; w < WPR; w += 1024) g_keptMaskG[w] = keptMask[w];
}

// ------------------------------- launcher ----------------------------------
extern "C" void kernel_launch(void* const* d_in, const int* in_sizes, int n_in,
                              void* d_out, int out_size) {
    const float* anchors = (const float*)d_in[0];
    const float* offsets = (const float*)d_in[1];
    const float* scores  = (const float*)d_in[2];
    const int*   ph      = (const int*)d_in[3];
    const int*   pw      = (const int*)d_in[4];
    const int*   ps      = (const int*)d_in[5];
    float* out = (float*)d_out;

    int n = in_sizes[2];
    if (n > NMAX) n = NMAX;
    int nb = (n + 255) / 256;

    k_zero<<<128, 256>>>(out);
    k_decode<<<nb, 256>>>(anchors, offsets, scores, ph, pw, ps, n);
    k_find1<<<1, 1024>>>();
    k_hist2<<<nb, 256>>>(n);
    k_find2<<<1, 1024>>>();
    k_gather<<<nb, 256>>>(n);
    k_rank<<<CAP / 256, 256>>>();

    // stage-1 NMS mask: first B1 ranks (always)
    k_mask<<<dim3(B1 / 64, B1 / 64), 64>>>(0, 0);
    k_resolve<<<1, 1024>>>(0, out);

    // stage-2 (rare): remaining ranks, gated on g_needMore
    k_mask<<<dim3(WPR, WPR - B1 / 64), 64>>>(B1 / 64, 1);
    k_resolve<<<1, 1024>>>(1, out);
}

// round 8
// speedup vs baseline: 1.1956x; 1.1956x over previous
#include <cuda_runtime.h>
#include <stdint.h>
#include <math.h>

// ---------------------------------------------------------------------------
// ProposalLayer: decode -> clip -> min-size filter -> top-12000 -> NMS(0.7)
//                -> first 2000 kept boxes (zero padded)
// R7: rank 8-way split (512 blocks), pipelined resolve, gated hist2/find2,
//     warp-aggregated gather atomics, small gated stage-2 stubs.
// ---------------------------------------------------------------------------

#define NMAX    147456
#define NPRE    12000
#define NPOST   2000
#define CAP     16384
#define NMS_T   0.7f
#define WPR     188          // u64 words per mask row (ceil(12000/64))
#define TOPPAD  12032        // 188*64
#define B1      4096         // stage-1 NMS coverage (64 chunks)
#define JSPLIT  8

// ------------------------- scratch (device globals) ------------------------
__device__ unsigned int       g_keys[NMAX];
__device__ float4             g_boxes[NMAX];
__device__ int                g_hist1[65536];
__device__ int                g_hist2[65536];
__device__ unsigned int       g_T;
__device__ int                g_C1;
__device__ int                g_flag;
__device__ int                g_need2;
__device__ unsigned int       g_kthKey;
__device__ int                g_candCount;
__device__ unsigned long long g_cand[CAP];
__device__ int                g_rank[CAP];
__device__ float4             g_topBox[TOPPAD];
__device__ float              g_topArea[TOPPAD];
__device__ int                g_validTop;
__device__ unsigned long long g_mask[(size_t)NPRE * WPR];   // ~18 MB
__device__ int                g_kept;
__device__ int                g_needMore;
__device__ unsigned long long g_keptMaskG[WPR];

// ------------------------------- K0: zero ----------------------------------
__global__ void k_zero(float* __restrict__ out) {
    int i = blockIdx.x * blockDim.x + threadIdx.x;
    int stride = gridDim.x * blockDim.x;
    for (int k = i; k < 65536; k += stride) { g_hist1[k] = 0; g_hist2[k] = 0; }
    for (int k = i; k < NPOST * 4; k += stride) out[k] = 0.0f;
    for (int k = i; k < CAP; k += stride) g_rank[k] = 0;
    if (i == 0) {
        g_candCount = 0;
        g_flag      = 0;
        g_need2     = 0;
        g_T         = 0;
        g_C1        = 0;
        g_kthKey    = 1u;      // fallback: gather all valid (only if <NPRE valid)
        g_needMore  = 0;
        g_kept      = 0;
    }
}

// --------------------- K1: decode + clip + key + hist1 ---------------------
__global__ void k_decode(const float* __restrict__ anc,
                         const float* __restrict__ off,
                         const float* __restrict__ sc,
                         const int* __restrict__ ph,
                         const int* __restrict__ pw,
                         const int* __restrict__ ps,
                         int n) {
    int i = blockIdx.x * blockDim.x + threadIdx.x;
    if (i >= n) return;

    float H = (float)ph[0];
    float W = (float)pw[0];
    float minsz = __fmul_rn(16.0f, (float)ps[0]);

    float a0 = anc[4 * i + 0], a1 = anc[4 * i + 1];
    float a2 = anc[4 * i + 2], a3 = anc[4 * i + 3];
    float o0 = off[4 * i + 0], o1 = off[4 * i + 1];
    float o2 = off[4 * i + 2], o3 = off[4 * i + 3];

    float ah  = __fsub_rn(a2, a0);
    float aw  = __fsub_rn(a3, a1);
    float acy = __fadd_rn(a0, __fmul_rn(0.5f, ah));
    float acx = __fadd_rn(a1, __fmul_rn(0.5f, aw));
    float cy  = __fadd_rn(__fmul_rn(o0, ah), acy);
    float cx  = __fadd_rn(__fmul_rn(o1, aw), acx);
    float h   = __fmul_rn(expf(o2), ah);
    float w   = __fmul_rn(expf(o3), aw);

    float y1 = __fsub_rn(cy, __fmul_rn(0.5f, h));
    float x1 = __fsub_rn(cx, __fmul_rn(0.5f, w));
    float y2 = __fadd_rn(cy, __fmul_rn(0.5f, h));
    float x2 = __fadd_rn(cx, __fmul_rn(0.5f, w));

    y1 = fminf(fmaxf(y1, 0.0f), H);
    x1 = fminf(fmaxf(x1, 0.0f), W);
    y2 = fminf(fmaxf(y2, 0.0f), H);
    x2 = fminf(fmaxf(x2, 0.0f), W);

    float rh = __fsub_rn(y2, y1);
    float rw = __fsub_rn(x2, x1);
    bool valid = (rh >= minsz) && (rw >= minsz);

    unsigned key = 0u;
    if (valid) {
        unsigned u = __float_as_uint(sc[i]);
        key = (u & 0x80000000u) ? ~u : (u | 0x80000000u);
        if (key == 0u) key = 1u;
    }
    g_keys[i]  = key;
    g_boxes[i] = make_float4(y1, x1, y2, x2);
    if (key) atomicAdd(&g_hist1[key >> 16], 1);
}

// -------- K2: find threshold bucket; set kthKey or request refinement ------
__global__ void k_find1() {
    __shared__ int part[1024];
    int t = threadIdx.x;
    const int4* h4 = (const int4*)g_hist1;
    int s = 0;
#pragma unroll
    for (int k = 0; k < 16; k++) {
        int4 v = h4[t * 16 + k];
        s += v.x + v.y + v.z + v.w;
    }
    part[t] = s;
    __syncthreads();
    for (int offs = 1; offs < 1024; offs <<= 1) {
        int v = part[t] + ((t + offs < 1024) ? part[t + offs] : 0);
        __syncthreads();
        part[t] = v;
        __syncthreads();
    }
    int Sincl = part[t];
    int Sexcl = Sincl - s;
    if (t == 0 && part[0] < NPRE) g_flag = 1;
    if (Sexcl < NPRE && Sincl >= NPRE) {
        int base = t * 64;
        int cum = Sexcl;
        for (int b = base + 63; b >= base; b--) {
            int hb = g_hist1[b];
            cum += hb;
            if (cum >= NPRE) {
                g_T  = (unsigned)b;
                g_C1 = cum - hb;
                // bucket-floor gather: m = C1 + hb candidates
                if (cum - hb + hb <= CAP && (cum - hb) + hb <= CAP) {
                    g_kthKey = ((unsigned)b) << 16;
                    if (g_kthKey == 0u) g_kthKey = 1u;   // key==0 is invalid anyway
                } else {
                    g_need2 = 1;    // too many in bucket: refine with low 16 bits
                }
                break;
            }
        }
    }
}

// ------------- K3 (gated): second-level histogram (16 low bits) ------------
__global__ void k_hist2(int n) {
    if (!g_need2) return;
    int i = blockIdx.x * blockDim.x + threadIdx.x;
    if (i >= n) return;
    unsigned key = g_keys[i];
    if (key && (key >> 16) == g_T) atomicAdd(&g_hist2[key & 0xFFFFu], 1);
}

// ---------------- K4 (gated): exact 32-bit K-th key ------------------------
__global__ void k_find2() {
    if (!g_need2) return;
    __shared__ int part[1024];
    int t = threadIdx.x;
    int C1 = g_C1;
    const int4* h4 = (const int4*)g_hist2;
    int s = 0;
#pragma unroll
    for (int k = 0; k < 16; k++) {
        int4 v = h4[t * 16 + k];
        s += v.x + v.y + v.z + v.w;
    }
    part[t] = s;
    __syncthreads();
    for (int offs = 1; offs < 1024; offs <<= 1) {
        int v = part[t] + ((t + offs < 1024) ? part[t + offs] : 0);
        __syncthreads();
        part[t] = v;
        __syncthreads();
    }
    int Sincl = part[t];
    int Sexcl = Sincl - s;
    if (C1 + Sexcl < NPRE && C1 + Sincl >= NPRE) {
        int base = t * 64;
        int cum = C1 + Sexcl;
        for (int b = base + 63; b >= base; b--) {
            cum += g_hist2[b];
            if (cum >= NPRE) {
                g_kthKey = (g_T << 16) | (unsigned)b;
                break;
            }
        }
    }
}

// ---------------- K5: gather (warp-aggregated atomics) ---------------------
__global__ void k_gather(int n) {
    int i = blockIdx.x * blockDim.x + threadIdx.x;
    unsigned key = (i < n) ? g_keys[i] : 0u;
    unsigned kth = g_kthKey;
    bool want = key && key >= kth;
    unsigned bal = __ballot_sync(0xffffffffu, want);
    if (!bal) return;
    int lane = threadIdx.x & 31;
    int leader = __ffs(bal) - 1;
    int base = 0;
    if (lane == leader) base = atomicAdd(&g_candCount, __popc(bal));
    base = __shfl_sync(0xffffffffu, base, leader);
    if (want) {
        int p = base + __popc(bal & ((1u << lane) - 1u));
        if (p < CAP) {
            // composite: score key desc, then index asc (top_k tie-break)
            g_cand[p] = ((unsigned long long)key << 32) |
                        (unsigned long long)(0xFFFFFFFFu - (unsigned)i);
        }
    }
}

// ---------- K6: partial brute-force rank, j split 8 ways (512 blocks) ------
__global__ void __launch_bounds__(256) k_rank_part() {
    __shared__ unsigned long long tile[256];
    int m = g_candCount; if (m > CAP) m = CAP;
    int j0 = blockIdx.y * (CAP / JSPLIT);
    if (j0 >= m) return;
    int j1 = j0 + (CAP / JSPLIT); if (j1 > m) j1 = m;
    int i = blockIdx.x * 256 + threadIdx.x;
    unsigned long long my = (i < m) ? g_cand[i] : 0ull;

    int r = 0;
    for (int jb = j0; jb < j1; jb += 256) {
        int j = jb + threadIdx.x;
        tile[threadIdx.x] = (j < j1) ? g_cand[j] : 0ull;
        __syncthreads();
        int lim = j1 - jb;
        if (lim >= 256) {
#pragma unroll 16
            for (int k = 0; k < 256; k++) r += (tile[k] > my) ? 1 : 0;
        } else {
            for (int k = 0; k < lim; k++) r += (tile[k] > my) ? 1 : 0;
        }
        __syncthreads();
    }
    if (i < m && r) atomicAdd(&g_rank[i], r);
}

// ------------------- K6b: scatter boxes/areas by rank ----------------------
__global__ void k_scatter() {
    int m = g_candCount; if (m > CAP) m = CAP;
    int i = blockIdx.x * 256 + threadIdx.x;
    if (i == 0) g_validTop = (m < NPRE) ? m : NPRE;
    if (i >= m) return;
    int rank = g_rank[i];
    if (rank >= NPRE) return;
    unsigned long long my = g_cand[i];
    unsigned idx = 0xFFFFFFFFu - (unsigned)my;
    float4 b = g_boxes[idx];
    g_topBox[rank]  = b;
    g_topArea[rank] = __fmul_rn(__fsub_rn(b.z, b.x), __fsub_rn(b.w, b.y));
}

// --------------------------- IoU (reference-exact) -------------------------
__device__ __forceinline__ bool iou_gt(float4 a, float aa, float4 b, float ab) {
    float ty = fmaxf(a.x, b.x);
    float tx = fmaxf(a.y, b.y);
    float by = fminf(a.z, b.z);
    float bx = fminf(a.w, b.w);
    float hh = fmaxf(__fsub_rn(by, ty), 0.0f);
    float ww = fmaxf(__fsub_rn(bx, tx), 0.0f);
    float inter = __fmul_rn(hh, ww);
    float uni = __fsub_rn(__fadd_rn(aa, ab), inter);
    float iou = __fdiv_rn(inter, fmaxf(uni, 1e-9f));
    return iou > NMS_T;
}

// ------ K7: stage-1 suppression mask (64x64 tiles, full words, rb<64) ------
__global__ void k_mask(float*) {
    int rb = blockIdx.y;
    int cb = blockIdx.x;
    if (cb > rb) return;

    __shared__ float4 cB[64];
    __shared__ float  cA[64];
    int t = threadIdx.x;
    cB[t] = g_topBox[cb * 64 + t];
    cA[t] = g_topArea[cb * 64 + t];
    __syncthreads();

    int row = rb * 64 + t;
    float4 rbx = g_topBox[row];
    float  ra  = g_topArea[row];

    unsigned long long word = 0ull;
    int jmax = (cb == rb) ? t : 64;
    for (int j = 0; j < jmax; j++)
        if (iou_gt(rbx, ra, cB[j], cA[j])) word |= (1ull << j);
    g_mask[(size_t)row * WPR + cb] = word;
}

// ------ K7b (gated): stage-2 mask, rows [B1, NPRE), looped rb grid ---------
__global__ void k_mask2() {
    if (!g_needMore) return;
    __shared__ float4 cB[64];
    __shared__ float  cA[64];
    int t = threadIdx.x;
    int cb = blockIdx.x;
    cB[t] = g_topBox[cb * 64 + t];
    cA[t] = g_topArea[cb * 64 + t];
    __syncthreads();

    for (int rb = B1 / 64 + blockIdx.y; rb < WPR; rb += 16) {
        if (cb > rb) continue;
        int row = rb * 64 + t;
        if (row >= NPRE) continue;
        float4 rbx = g_topBox[row];
        float  ra  = g_topArea[row];
        unsigned long long word = 0ull;
        int jmax = (cb == rb) ? t : 64;
        for (int j = 0; j < jmax; j++)
            if (iou_gt(rbx, ra, cB[j], cA[j])) word |= (1ull << j);
        g_mask[(size_t)row * WPR + cb] = word;
    }
}

// ------ K8: pipelined greedy resolve over precomputed mask (IoU-free) ------
__global__ void __launch_bounds__(1024, 1) k_resolve(int stage, float* __restrict__ out) {
    if (stage && !g_needMore) return;

    __shared__ unsigned long long keptMask[WPR];
    __shared__ unsigned long long lastW[2][64];
    __shared__ unsigned long long diagW[2][64];
    __shared__ int                supH[2][64];
    __shared__ int                sup[64];
    __shared__ unsigned long long sKl;
    __shared__ int                sKept;

    int tid  = threadIdx.x;
    int lane = tid & 31;
    int warp = tid >> 5;   // 32 warps

    int vt = g_validTop;
    int start = stage ? B1 : 0;
    int end   = stage ? vt : (vt < B1 ? vt : B1);
    int kept  = stage ? g_kept : 0;

    if (stage) { for (int w = tid; w < WPR; w += 1024) keptMask[w] = g_keptMaskG[w]; }
    else       { for (int w = tid; w < WPR; w += 1024) keptMask[w] = 0ull; }
    __syncthreads();

    int cw0 = start >> 6;
    // prologue: prefetch buffers (slot 0) for the first chunk
    {
        int cn = end - start; if (cn > 64) cn = 64;
        for (int r = warp; r < cn; r += 32) {
            const unsigned long long* rowp = &g_mask[(size_t)(start + r) * WPR];
            bool any = false;
            for (int w = lane; w < cw0 - 1; w += 32)
                any |= (__ldg(rowp + w) & keptMask[w]) != 0ull;
            unsigned bal = __ballot_sync(0xffffffffu, any);
            if (lane == 0) {
                supH[0][r]  = (bal != 0u);
                lastW[0][r] = (cw0 > 0) ? __ldg(rowp + (cw0 - 1)) : 0ull;
                diagW[0][r] = __ldg(rowp + cw0);
            }
        }
    }
    unsigned long long klPrev = (cw0 > 0) ? keptMask[cw0 - 1] : 0ull;
    __syncthreads();

    int pb = 0;
    for (int base = start; base < end && kept < NPOST; base += 64, pb ^= 1) {
        int cw = base >> 6;
        int cn = end - base; if (cn > 64) cn = 64;

        // 1. combine: supPrev for this chunk (smem-only, no memory latency)
        if (tid < cn)
            sup[tid] = supH[pb][tid] | (((lastW[pb][tid] & klPrev) != 0ull) ? 1 : 0);

        // 2. prefetch next chunk into other slot (uses only published keptMask words)
        int nbase = base + 64;
        if (nbase < end) {
            int ncn = end - nbase; if (ncn > 64) ncn = 64;
            for (int r = warp; r < ncn; r += 32) {
                const unsigned long long* rowp = &g_mask[(size_t)(nbase + r) * WPR];
                bool any = false;
                for (int w = lane; w < cw; w += 32)
                    any |= (__ldg(rowp + w) & keptMask[w]) != 0ull;
                unsigned bal = __ballot_sync(0xffffffffu, any);
                if (lane == 0) {
                    supH[pb ^ 1][r]  = (bal != 0u);
                    lastW[pb ^ 1][r] = __ldg(rowp + cw);
                    diagW[pb ^ 1][r] = __ldg(rowp + cw + 1);
                }
            }
        }
        __syncthreads();

        // 3. exact sequential greedy within the 64-chunk
        if (tid == 0) {
            unsigned long long kl = 0ull;
            int kc = kept;
            for (int i2 = 0; i2 < cn && kc < NPOST; i2++) {
                if (!sup[i2] && !(diagW[pb][i2] & kl)) { kl |= (1ull << i2); kc++; }
            }
            sKl = kl; sKept = kc;
            keptMask[cw] = kl;
        }
        __syncthreads();

        unsigned long long kl = sKl;
        if (tid < cn && ((kl >> tid) & 1ull)) {
            int pos = kept + __popcll(kl & ((1ull << tid) - 1ull));
            ((float4*)out)[pos] = g_topBox[base + tid];
        }
        kept = sKept;
        klPrev = kl;
        __syncthreads();
    }

    if (tid == 0) {
        g_kept = kept;
        if (stage == 0) g_needMore = (kept < NPOST && vt > B1) ? 1 : 0;
    }
    for (int w = tid; w < WPR; w += 1024) g_keptMaskG[w] = keptMask[w];
}

// ------------------------------- launcher ----------------------------------
extern "C" void kernel_launch(void* const* d_in, const int* in_sizes, int n_in,
                              void* d_out, int out_size) {
    const float* anchors = (const float*)d_in[0];
    const float* offsets = (const float*)d_in[1];
    const float* scores  = (const float*)d_in[2];
    const int*   ph      = (const int*)d_in[3];
    const int*   pw      = (const int*)d_in[4];
    const int*   ps      = (const int*)d_in[5];
    float* out = (float*)d_out;

    int n = in_sizes[2];
    if (n > NMAX) n = NMAX;
    int nb = (n + 255) / 256;

    k_zero<<<128, 256>>>(out);
    k_decode<<<nb, 256>>>(anchors, offsets, scores, ph, pw, ps, n);
    k_find1<<<1, 1024>>>();
    k_hist2<<<nb, 256>>>(n);          // gated on g_need2
    k_find2<<<1, 1024>>>();           // gated on g_need2
    k_gather<<<nb, 256>>>(n);
    k_rank_part<<<dim3(64, JSPLIT), 256>>>();
    k_scatter<<<64, 256>>>();

    k_mask<<<dim3(64, 64), 64>>>(out);
    k_resolve<<<1, 1024>>>(0, out);

    k_mask2<<<dim3(WPR, 16), 64>>>(); // gated on g_needMore
    k_resolve<<<1, 1024>>>(1, out);
}

// round 9
// speedup vs baseline: 1.4398x; 1.2043x over previous
#include <cuda_runtime.h>
#include <stdint.h>
#include <math.h>

// ---------------------------------------------------------------------------
// ProposalLayer: decode -> clip -> min-size filter -> top-12000 -> NMS(0.7)
//                -> first 2000 kept boxes (zero padded)
// R8: warp-specialized single-barrier resolve with parallel-greedy frontier,
//     rank+scatter merged (completion counter), float4 decode, smaller stubs.
// ---------------------------------------------------------------------------

#define NMAX    147456
#define NPRE    12000
#define NPOST   2000
#define CAP     16384
#define NMS_T   0.7f
#define WPR     188          // u64 words per mask row (ceil(12000/64))
#define TOPPAD  12032        // 188*64
#define B1      4096         // stage-1 NMS coverage (64 chunks)
#define JSPLIT  8

// ------------------------- scratch (device globals) ------------------------
__device__ unsigned int       g_keys[NMAX];
__device__ float4             g_boxes[NMAX];
__device__ int                g_hist1[65536];
__device__ int                g_hist2[65536];
__device__ unsigned int       g_T;
__device__ int                g_C1;
__device__ int                g_flag;
__device__ int                g_need2;
__device__ unsigned int       g_kthKey;
__device__ int                g_candCount;
__device__ int                g_rankDone;
__device__ unsigned long long g_cand[CAP];
__device__ int                g_rank[CAP];
__device__ float4             g_topBox[TOPPAD];
__device__ float              g_topArea[TOPPAD];
__device__ int                g_validTop;
__device__ unsigned long long g_mask[(size_t)NPRE * WPR];   // ~18 MB
__device__ int                g_kept;
__device__ int                g_needMore;
__device__ unsigned long long g_keptMaskG[WPR];

// ------------------------------- K0: zero ----------------------------------
__global__ void k_zero(float* __restrict__ out) {
    int i = blockIdx.x * blockDim.x + threadIdx.x;
    int stride = gridDim.x * blockDim.x;
    for (int k = i; k < 65536; k += stride) { g_hist1[k] = 0; g_hist2[k] = 0; }
    for (int k = i; k < NPOST * 4; k += stride) out[k] = 0.0f;
    for (int k = i; k < CAP; k += stride) g_rank[k] = 0;
    if (i == 0) {
        g_candCount = 0;
        g_flag      = 0;
        g_need2     = 0;
        g_T         = 0;
        g_C1        = 0;
        g_kthKey    = 1u;      // fallback: gather all valid (only if <NPRE valid)
        g_needMore  = 0;
        g_kept      = 0;
        g_rankDone  = 0;
    }
}

// --------------------- K1: decode + clip + key + hist1 ---------------------
__global__ void k_decode(const float4* __restrict__ anc4,
                         const float4* __restrict__ off4,
                         const float* __restrict__ sc,
                         const int* __restrict__ ph,
                         const int* __restrict__ pw,
                         const int* __restrict__ ps,
                         int n) {
    int i = blockIdx.x * blockDim.x + threadIdx.x;
    if (i >= n) return;

    float H = (float)ph[0];
    float W = (float)pw[0];
    float minsz = __fmul_rn(16.0f, (float)ps[0]);

    float4 a = anc4[i];
    float4 o = off4[i];

    float ah  = __fsub_rn(a.z, a.x);
    float aw  = __fsub_rn(a.w, a.y);
    float acy = __fadd_rn(a.x, __fmul_rn(0.5f, ah));
    float acx = __fadd_rn(a.y, __fmul_rn(0.5f, aw));
    float cy  = __fadd_rn(__fmul_rn(o.x, ah), acy);
    float cx  = __fadd_rn(__fmul_rn(o.y, aw), acx);
    float h   = __fmul_rn(expf(o.z), ah);
    float w   = __fmul_rn(expf(o.w), aw);

    float y1 = __fsub_rn(cy, __fmul_rn(0.5f, h));
    float x1 = __fsub_rn(cx, __fmul_rn(0.5f, w));
    float y2 = __fadd_rn(cy, __fmul_rn(0.5f, h));
    float x2 = __fadd_rn(cx, __fmul_rn(0.5f, w));

    y1 = fminf(fmaxf(y1, 0.0f), H);
    x1 = fminf(fmaxf(x1, 0.0f), W);
    y2 = fminf(fmaxf(y2, 0.0f), H);
    x2 = fminf(fmaxf(x2, 0.0f), W);

    float rh = __fsub_rn(y2, y1);
    float rw = __fsub_rn(x2, x1);
    bool valid = (rh >= minsz) && (rw >= minsz);

    unsigned key = 0u;
    if (valid) {
        unsigned u = __float_as_uint(sc[i]);
        key = (u & 0x80000000u) ? ~u : (u | 0x80000000u);
        if (key == 0u) key = 1u;
    }
    g_keys[i]  = key;
    g_boxes[i] = make_float4(y1, x1, y2, x2);
    if (key) atomicAdd(&g_hist1[key >> 16], 1);
}

// -------- K2: find threshold bucket; set kthKey or request refinement ------
__global__ void k_find1() {
    __shared__ int part[1024];
    int t = threadIdx.x;
    const int4* h4 = (const int4*)g_hist1;
    int s = 0;
#pragma unroll
    for (int k = 0; k < 16; k++) {
        int4 v = h4[t * 16 + k];
        s += v.x + v.y + v.z + v.w;
    }
    part[t] = s;
    __syncthreads();
    for (int offs = 1; offs < 1024; offs <<= 1) {
        int v = part[t] + ((t + offs < 1024) ? part[t + offs] : 0);
        __syncthreads();
        part[t] = v;
        __syncthreads();
    }
    int Sincl = part[t];
    int Sexcl = Sincl - s;
    if (t == 0 && part[0] < NPRE) g_flag = 1;
    if (Sexcl < NPRE && Sincl >= NPRE) {
        int base = t * 64;
        int cum = Sexcl;
        for (int b = base + 63; b >= base; b--) {
            int hb = g_hist1[b];
            cum += hb;
            if (cum >= NPRE) {
                g_T  = (unsigned)b;
                g_C1 = cum - hb;
                if (cum <= CAP) {
                    // bucket-floor gather: m = cum candidates fits CAP
                    unsigned kk = ((unsigned)b) << 16;
                    g_kthKey = kk ? kk : 1u;
                } else {
                    g_need2 = 1;    // refine with low 16 bits
                }
                break;
            }
        }
    }
}

// ------------- K3 (gated): second-level histogram (16 low bits) ------------
__global__ void k_hist2(int n) {
    if (!g_need2) return;
    int stride = gridDim.x * blockDim.x;
    for (int i = blockIdx.x * blockDim.x + threadIdx.x; i < n; i += stride) {
        unsigned key = g_keys[i];
        if (key && (key >> 16) == g_T) atomicAdd(&g_hist2[key & 0xFFFFu], 1);
    }
}

// ---------------- K4 (gated): exact 32-bit K-th key ------------------------
__global__ void k_find2() {
    if (!g_need2) return;
    __shared__ int part[1024];
    int t = threadIdx.x;
    int C1 = g_C1;
    const int4* h4 = (const int4*)g_hist2;
    int s = 0;
#pragma unroll
    for (int k = 0; k < 16; k++) {
        int4 v = h4[t * 16 + k];
        s += v.x + v.y + v.z + v.w;
    }
    part[t] = s;
    __syncthreads();
    for (int offs = 1; offs < 1024; offs <<= 1) {
        int v = part[t] + ((t + offs < 1024) ? part[t + offs] : 0);
        __syncthreads();
        part[t] = v;
        __syncthreads();
    }
    int Sincl = part[t];
    int Sexcl = Sincl - s;
    if (C1 + Sexcl < NPRE && C1 + Sincl >= NPRE) {
        int base = t * 64;
        int cum = C1 + Sexcl;
        for (int b = base + 63; b >= base; b--) {
            cum += g_hist2[b];
            if (cum >= NPRE) {
                g_kthKey = (g_T << 16) | (unsigned)b;
                break;
            }
        }
    }
}

// ---------------- K5: gather (warp-aggregated atomics) ---------------------
__global__ void k_gather(int n) {
    int i = blockIdx.x * blockDim.x + threadIdx.x;
    unsigned key = (i < n) ? g_keys[i] : 0u;
    unsigned kth = g_kthKey;
    bool want = key && key >= kth;
    unsigned bal = __ballot_sync(0xffffffffu, want);
    if (!bal) return;
    int lane = threadIdx.x & 31;
    int leader = __ffs(bal) - 1;
    int base = 0;
    if (lane == leader) base = atomicAdd(&g_candCount, __popc(bal));
    base = __shfl_sync(0xffffffffu, base, leader);
    if (want) {
        int p = base + __popc(bal & ((1u << lane) - 1u));
        if (p < CAP) {
            // composite: score key desc, then index asc (top_k tie-break)
            g_cand[p] = ((unsigned long long)key << 32) |
                        (unsigned long long)(0xFFFFFFFFu - (unsigned)i);
        }
    }
}

// ------ K6: partial rank (j split 8 ways) + last-block scatter -------------
__global__ void __launch_bounds__(256) k_rankscatter() {
    __shared__ unsigned long long tile[256];
    __shared__ int sLastBlk;
    int m = g_candCount; if (m > CAP) m = CAP;
    int j0 = blockIdx.y * (CAP / JSPLIT);
    int i = blockIdx.x * 256 + threadIdx.x;

    if (j0 < m) {
        int j1 = j0 + (CAP / JSPLIT); if (j1 > m) j1 = m;
        unsigned long long my = (i < m) ? g_cand[i] : 0ull;
        int r = 0;
        for (int jb = j0; jb < j1; jb += 256) {
            int j = jb + threadIdx.x;
            tile[threadIdx.x] = (j < j1) ? g_cand[j] : 0ull;
            __syncthreads();
            int lim = j1 - jb;
            if (lim >= 256) {
#pragma unroll 16
                for (int k = 0; k < 256; k++) r += (tile[k] > my) ? 1 : 0;
            } else {
                for (int k = 0; k < lim; k++) r += (tile[k] > my) ? 1 : 0;
            }
            __syncthreads();
        }
        if (i < m && r) atomicAdd(&g_rank[i], r);
    }

    __threadfence();
    __syncthreads();
    if (threadIdx.x == 0)
        sLastBlk = (atomicAdd(&g_rankDone, 1) == (int)(gridDim.x * gridDim.y) - 1);
    __syncthreads();
    if (!sLastBlk) return;

    // last block: scatter boxes/areas by final rank
    for (int k = threadIdx.x; k < m; k += 256) {
        int rank = __ldcg(&g_rank[k]);
        if (rank < NPRE) {
            unsigned long long my = g_cand[k];
            unsigned idx = 0xFFFFFFFFu - (unsigned)my;
            float4 b = g_boxes[idx];
            g_topBox[rank]  = b;
            g_topArea[rank] = __fmul_rn(__fsub_rn(b.z, b.x), __fsub_rn(b.w, b.y));
        }
    }
    if (threadIdx.x == 0) g_validTop = (m < NPRE) ? m : NPRE;
}

// --------------------------- IoU (reference-exact) -------------------------
__device__ __forceinline__ bool iou_gt(float4 a, float aa, float4 b, float ab) {
    float ty = fmaxf(a.x, b.x);
    float tx = fmaxf(a.y, b.y);
    float by = fminf(a.z, b.z);
    float bx = fminf(a.w, b.w);
    float hh = fmaxf(__fsub_rn(by, ty), 0.0f);
    float ww = fmaxf(__fsub_rn(bx, tx), 0.0f);
    float inter = __fmul_rn(hh, ww);
    float uni = __fsub_rn(__fadd_rn(aa, ab), inter);
    float iou = __fdiv_rn(inter, fmaxf(uni, 1e-9f));
    return iou > NMS_T;
}

// ------ K7: stage-1 suppression mask (64x64 tiles, full words, rb<64) ------
__global__ void k_mask() {
    int rb = blockIdx.y;
    int cb = blockIdx.x;
    if (cb > rb) return;

    __shared__ float4 cB[64];
    __shared__ float  cA[64];
    int t = threadIdx.x;
    cB[t] = g_topBox[cb * 64 + t];
    cA[t] = g_topArea[cb * 64 + t];
    __syncthreads();

    int row = rb * 64 + t;
    float4 rbx = g_topBox[row];
    float  ra  = g_topArea[row];

    unsigned long long word = 0ull;
    int jmax = (cb == rb) ? t : 64;
    for (int j = 0; j < jmax; j++)
        if (iou_gt(rbx, ra, cB[j], cA[j])) word |= (1ull << j);
    g_mask[(size_t)row * WPR + cb] = word;
}

// ------ K7b (gated): stage-2 mask, rows [B1, NPRE), looped rb grid ---------
__global__ void k_mask2() {
    if (!g_needMore) return;
    __shared__ float4 cB[64];
    __shared__ float  cA[64];
    int t = threadIdx.x;
    int cb = blockIdx.x;
    cB[t] = g_topBox[cb * 64 + t];
    cA[t] = g_topArea[cb * 64 + t];
    __syncthreads();

    for (int rb = B1 / 64 + blockIdx.y; rb < WPR; rb += 4) {
        if (cb > rb) continue;
        int row = rb * 64 + t;
        if (row >= NPRE) continue;
        float4 rbx = g_topBox[row];
        float  ra  = g_topArea[row];
        unsigned long long word = 0ull;
        int jmax = (cb == rb) ? t : 64;
        for (int j = 0; j < jmax; j++)
            if (iou_gt(rbx, ra, cB[j], cA[j])) word |= (1ull << j);
        g_mask[(size_t)row * WPR + cb] = word;
    }
}

// ------ K8: warp-specialized resolve: warp0 greedy | warps1-13 prefetch ----
// Exact parallel greedy per 64-chunk via frontier rounds; 1 barrier/chunk.
__global__ void __launch_bounds__(512, 1) k_resolve(int stage, float* __restrict__ out) {
    if (stage && !g_needMore) return;

    __shared__ unsigned long long keptMask[WPR];
    __shared__ unsigned long long sLast[2][64];
    __shared__ unsigned long long sDiag[2][64];
    __shared__ unsigned long long sSupW[2][14];
    __shared__ int sKept, sStop;
    __shared__ int wordBase[WPR];

    int tid = threadIdx.x, lane = tid & 31, warp = tid >> 5;   // 16 warps
    int vt = g_validTop;
    int start = stage ? B1 : 0;
    int end   = stage ? vt : (vt < B1 ? vt : B1);
    int kept0 = stage ? g_kept : 0;

    if (stage) { for (int w = tid; w < WPR; w += 512) keptMask[w] = g_keptMaskG[w]; }
    else       { for (int w = tid; w < WPR; w += 512) keptMask[w] = 0ull; }
    if (tid == 0) { sKept = kept0; sStop = (start >= end || kept0 >= NPOST) ? 1 : 0; }
    __syncthreads();

    if (!sStop) {
        // ---- prologue: prefetch first chunk into slot 0 (warps 1..13) ----
        {
            int base = start, cw = start >> 6;
            int cn = end - base; if (cn > 64) cn = 64;
            if (warp >= 1 && warp <= 13) {
                int r0 = (warp - 1) * 5;
                int r1 = r0 + 5; if (r1 > cn) r1 = cn;
                unsigned long long supbits = 0ull;
                for (int r = r0; r < r1; r++) {
                    const unsigned long long* rowp = &g_mask[(size_t)(base + r) * WPR];
                    bool any = false;
                    for (int w = lane; w < cw - 1; w += 32)
                        any |= (__ldg(rowp + w) & keptMask[w]) != 0ull;
                    unsigned bal = __ballot_sync(0xffffffffu, any);
                    if (lane == 0) {
                        if (bal) supbits |= 1ull << r;
                        sLast[0][r] = (cw > 0) ? __ldg(rowp + cw - 1) : 0ull;
                        sDiag[0][r] = __ldg(rowp + cw);
                    }
                }
                if (lane == 0) sSupW[0][warp] = supbits;
            }
        }
        __syncthreads();

        unsigned long long klPrev = (start >= 64) ? keptMask[(start >> 6) - 1] : 0ull;
        int kept = kept0;
        int pb = 0;
        for (int base = start; ; base += 64, pb ^= 1) {
            int cw = base >> 6;
            int cn = end - base; if (cn > 64) cn = 64;
            int nbase = base + 64;

            if (warp == 0) {
                // --- exact greedy on chunk in slot pb ---
                unsigned long long sup = (lane >= 1 && lane <= 13) ? sSupW[pb][lane] : 0ull;
#pragma unroll
                for (int o = 16; o; o >>= 1)
                    sup |= __shfl_xor_sync(0xffffffffu, sup, o);
                bool slo = (sLast[pb][lane]      & klPrev) != 0ull;
                bool shi = (sLast[pb][lane + 32] & klPrev) != 0ull;
                sup |= (unsigned long long)__ballot_sync(0xffffffffu, slo)
                     | ((unsigned long long)__ballot_sync(0xffffffffu, shi) << 32);
                unsigned long long cand = ~sup;
                if (cn < 64) cand &= (1ull << cn) - 1ull;
                unsigned long long rowLo = sDiag[pb][lane];
                unsigned long long rowHi = sDiag[pb][lane + 32];
                unsigned long long U = cand, K = 0ull;
                while (U) {   // frontier rounds == sequential greedy
                    bool flo = ((U >> lane) & 1ull) && ((rowLo & U) == 0ull);
                    bool fhi = ((U >> (lane + 32)) & 1ull) && ((rowHi & U) == 0ull);
                    unsigned long long F =
                          (unsigned long long)__ballot_sync(0xffffffffu, flo)
                        | ((unsigned long long)__ballot_sync(0xffffffffu, fhi) << 32);
                    K |= F;
                    bool qlo = (rowLo & F) != 0ull;
                    bool qhi = (rowHi & F) != 0ull;
                    unsigned long long S =
                          (unsigned long long)__ballot_sync(0xffffffffu, qlo)
                        | ((unsigned long long)__ballot_sync(0xffffffffu, qhi) << 32);
                    U &= ~(F | S | K);
                }
                int c = __popcll(K);
                int room = NPOST - kept;
                while (c > room) { K &= ~(1ull << (63 - __clzll(K))); c--; }
                kept += c;
                klPrev = K;
                if (lane == 0) {
                    keptMask[cw] = K;
                    sKept = kept;
                    sStop = (kept >= NPOST) ? 1 : 0;
                }
            } else if (warp <= 13 && nbase < end) {
                // --- prefetch next chunk into slot pb^1 ---
                int ncn = end - nbase; if (ncn > 64) ncn = 64;
                int r0 = (warp - 1) * 5;
                int r1 = r0 + 5; if (r1 > ncn) r1 = ncn;
                unsigned long long supbits = 0ull;
                for (int r = r0; r < r1; r++) {
                    const unsigned long long* rowp = &g_mask[(size_t)(nbase + r) * WPR];
                    bool any = false;
                    for (int w = lane; w < cw; w += 32)   // words [0, cw-1]
                        any |= (__ldg(rowp + w) & keptMask[w]) != 0ull;
                    unsigned bal = __ballot_sync(0xffffffffu, any);
                    if (lane == 0) {
                        if (bal) supbits |= 1ull << r;
                        sLast[pb ^ 1][r] = __ldg(rowp + cw);
                        sDiag[pb ^ 1][r] = __ldg(rowp + cw + 1);
                    }
                }
                if (lane == 0) sSupW[pb ^ 1][warp] = supbits;
            }
            __syncthreads();
            if (sStop || nbase >= end) break;
        }
    }
    __syncthreads();

    // ---- epilogue: prefix popcounts, then write all kept boxes in parallel
    if (warp == 0) {
        int carry = 0;
        for (int g = 0; g < WPR; g += 32) {
            int w = g + lane;
            int v = (w < WPR) ? __popcll(keptMask[w]) : 0;
            int incl = v;
#pragma unroll
            for (int o = 1; o < 32; o <<= 1) {
                int t2 = __shfl_up_sync(0xffffffffu, incl, o);
                if (lane >= o) incl += t2;
            }
            if (w < WPR) wordBase[w] = carry + incl - v;
            carry += __shfl_sync(0xffffffffu, incl, 31);
        }
    }
    __syncthreads();

    for (int p = tid; p < WPR * 64; p += 512) {
        int w = p >> 6, b = p & 63;
        unsigned long long km = keptMask[w];
        if ((km >> b) & 1ull) {
            int pos = wordBase[w] + __popcll(km & ((1ull << b) - 1ull));
            ((float4*)out)[pos] = g_topBox[w * 64 + b];
        }
    }

    if (tid == 0) {
        g_kept = sKept;
        if (stage == 0) g_needMore = (sKept < NPOST && vt > B1) ? 1 : 0;
    }
    for (int w = tid; w < WPR; w += 512) g_keptMaskG[w] = keptMask[w];
}

// ------------------------------- launcher ----------------------------------
extern "C" void kernel_launch(void* const* d_in, const int* in_sizes, int n_in,
                              void* d_out, int out_size) {
    const float* anchors = (const float*)d_in[0];
    const float* offsets = (const float*)d_in[1];
    const float* scores  = (const float*)d_in[2];
    const int*   ph      = (const int*)d_in[3];
    const int*   pw      = (const int*)d_in[4];
    const int*   ps      = (const int*)d_in[5];
    float* out = (float*)d_out;

    int n = in_sizes[2];
    if (n > NMAX) n = NMAX;
    int nb = (n + 255) / 256;

    k_zero<<<128, 256>>>(out);
    k_decode<<<nb, 256>>>((const float4*)anchors, (const float4*)offsets,
                          scores, ph, pw, ps, n);
    k_find1<<<1, 1024>>>();
    k_hist2<<<148, 256>>>(n);         // gated on g_need2
    k_find2<<<1, 1024>>>();           // gated on g_need2
    k_gather<<<nb, 256>>>(n);
    k_rankscatter<<<dim3(64, JSPLIT), 256>>>();

    k_mask<<<dim3(64, 64), 64>>>();
    k_resolve<<<1, 512>>>(0, out);

    k_mask2<<<dim3(WPR, 4), 64>>>();  // gated on g_needMore
    k_resolve<<<1, 512>>>(1, out);
}